// round 1
// baseline (speedup 1.0000x reference)
#include <cuda_runtime.h>
#include <cstdint>

#define B_   16
#define V_   20000
#define D_   256
#define H_   256
#define EPS_ 1e-5f

// ---------------- scratch (device globals; no allocation allowed) ----------------
__device__ float g_p[B_ * D_];        // LN'd patient proj (16x256)
__device__ float g_pht[H_ * B_];      // ph transposed [h][b], b1 folded in
__device__ float g_a[V_ * D_];        // LN'd atc4 proj (20000x256)
__device__ float g_ah[V_ * D_];       // a @ W1[D:]
__device__ float g_scores[B_ * V_];   // pre-LN scores [b][v]
__device__ float g_stats[2 * B_];     // mean, rstd per b

// ---------------- K1a: p = LN(pe @ Wp + bp; gp, betap) ----------------
// grid = 16 (b), block = 256 (d)
__global__ void k_patient_proj(const float* __restrict__ pe,
                               const float* __restrict__ Wp,
                               const float* __restrict__ bp,
                               const float* __restrict__ gp,
                               const float* __restrict__ betap)
{
    int b = blockIdx.x;
    int d = threadIdx.x;
    __shared__ float s_pe[D_];
    s_pe[d] = pe[b * D_ + d];
    __syncthreads();

    float acc = bp[d];
    #pragma unroll 8
    for (int k = 0; k < D_; k++)
        acc = fmaf(s_pe[k], Wp[k * D_ + d], acc);

    // block reduce sum & sumsq over 256 values
    float s1 = acc, s2 = acc * acc;
    #pragma unroll
    for (int o = 16; o; o >>= 1) {
        s1 += __shfl_xor_sync(0xffffffffu, s1, o);
        s2 += __shfl_xor_sync(0xffffffffu, s2, o);
    }
    __shared__ float r1[8], r2[8], bc[2];
    int w = d >> 5, l = d & 31;
    if (l == 0) { r1[w] = s1; r2[w] = s2; }
    __syncthreads();
    if (d == 0) {
        float t1 = 0.f, t2 = 0.f;
        #pragma unroll
        for (int i = 0; i < 8; i++) { t1 += r1[i]; t2 += r2[i]; }
        float mean = t1 * (1.0f / D_);
        float var  = t2 * (1.0f / D_) - mean * mean;
        bc[0] = mean;
        bc[1] = rsqrtf(var + EPS_);
    }
    __syncthreads();
    g_p[b * D_ + d] = (acc - bc[0]) * bc[1] * gp[d] + betap[d];
}

// ---------------- K1b: pht[h][b] = p[b] @ W1[:D][:,h] + b1[h] ----------------
// grid = 16 (b), block = 256 (h)
__global__ void k_patient_head(const float* __restrict__ W1,
                               const float* __restrict__ b1)
{
    int b = blockIdx.x;
    int h = threadIdx.x;
    __shared__ float s_p[D_];
    s_p[h] = g_p[b * D_ + h];
    __syncthreads();
    float acc = b1[h];
    #pragma unroll 8
    for (int k = 0; k < D_; k++)
        acc = fmaf(s_p[k], W1[k * H_ + h], acc);
    g_pht[h * B_ + b] = acc;
}

// ---------------- GEMM: C[M,256] = A[M,256] @ Bm[256,256] (+bias, +rowLN) ----------------
// BM=64, BN=256, BK=16, 256 threads, 8x8 per thread.
// Warp ty owns rows ty*8..ty*8+7 completely -> row-LN via warp shuffles.
template <bool DO_LN>
__global__ __launch_bounds__(256, 2)
void k_gemm(const float* __restrict__ A,
            const float* __restrict__ Bm,
            const float* __restrict__ bias,   // nullptr if !DO_LN
            const float* __restrict__ gamma,
            const float* __restrict__ beta,
            float* __restrict__ C, int M)
{
    __shared__ float As[16][64];
    __shared__ float Bs[16][256];

    int t  = threadIdx.x;
    int ty = t >> 5;        // warp 0..7
    int tx = t & 31;        // lane
    int m0 = blockIdx.x * 64;

    int a_row = t & 63;     // A-load row
    int a_k4  = t >> 6;     // A-load k-quad 0..3
    int b_n4  = t & 63;     // B-load col-quad
    int b_kb  = t >> 6;     // B-load k-block 0..3

    bool a_ok = (m0 + a_row) < M;

    float acc[8][8];
    #pragma unroll
    for (int j = 0; j < 8; j++)
        #pragma unroll
        for (int i = 0; i < 8; i++) acc[j][i] = 0.f;

    for (int kk = 0; kk < 256; kk += 16) {
        float4 av = a_ok
            ? *(const float4*)&A[(size_t)(m0 + a_row) * 256 + kk + a_k4 * 4]
            : make_float4(0.f, 0.f, 0.f, 0.f);
        float4 bv[4];
        #pragma unroll
        for (int q = 0; q < 4; q++)
            bv[q] = *(const float4*)&Bm[(size_t)(kk + b_kb * 4 + q) * 256 + b_n4 * 4];

        __syncthreads();   // prior tile fully consumed
        As[a_k4 * 4 + 0][a_row] = av.x;
        As[a_k4 * 4 + 1][a_row] = av.y;
        As[a_k4 * 4 + 2][a_row] = av.z;
        As[a_k4 * 4 + 3][a_row] = av.w;
        #pragma unroll
        for (int q = 0; q < 4; q++)
            *(float4*)&Bs[b_kb * 4 + q][b_n4 * 4] = bv[q];
        __syncthreads();

        #pragma unroll
        for (int k = 0; k < 16; k++) {
            float af[8], bf[8];
            *(float4*)&af[0] = *(const float4*)&As[k][ty * 8];
            *(float4*)&af[4] = *(const float4*)&As[k][ty * 8 + 4];
            *(float4*)&bf[0] = *(const float4*)&Bs[k][tx * 4];
            *(float4*)&bf[4] = *(const float4*)&Bs[k][128 + tx * 4];
            #pragma unroll
            for (int j = 0; j < 8; j++)
                #pragma unroll
                for (int i = 0; i < 8; i++)
                    acc[j][i] = fmaf(af[j], bf[i], acc[j][i]);
        }
    }

    if (DO_LN) {
        float4 ba0 = *(const float4*)&bias[tx * 4];
        float4 ba1 = *(const float4*)&bias[128 + tx * 4];
        float4 g0  = *(const float4*)&gamma[tx * 4];
        float4 g1  = *(const float4*)&gamma[128 + tx * 4];
        float4 be0 = *(const float4*)&beta[tx * 4];
        float4 be1 = *(const float4*)&beta[128 + tx * 4];
        #pragma unroll
        for (int j = 0; j < 8; j++) {
            float v[8];
            v[0] = acc[j][0] + ba0.x; v[1] = acc[j][1] + ba0.y;
            v[2] = acc[j][2] + ba0.z; v[3] = acc[j][3] + ba0.w;
            v[4] = acc[j][4] + ba1.x; v[5] = acc[j][5] + ba1.y;
            v[6] = acc[j][6] + ba1.z; v[7] = acc[j][7] + ba1.w;
            float s1 = 0.f, s2 = 0.f;
            #pragma unroll
            for (int i = 0; i < 8; i++) { s1 += v[i]; s2 = fmaf(v[i], v[i], s2); }
            #pragma unroll
            for (int o = 16; o; o >>= 1) {
                s1 += __shfl_xor_sync(0xffffffffu, s1, o);
                s2 += __shfl_xor_sync(0xffffffffu, s2, o);
            }
            float mean = s1 * (1.0f / 256.0f);
            float var  = s2 * (1.0f / 256.0f) - mean * mean;
            float rstd = rsqrtf(var + EPS_);
            int row = m0 + ty * 8 + j;
            if (row < M) {
                float4 o0, o1;
                o0.x = (v[0] - mean) * rstd * g0.x + be0.x;
                o0.y = (v[1] - mean) * rstd * g0.y + be0.y;
                o0.z = (v[2] - mean) * rstd * g0.z + be0.z;
                o0.w = (v[3] - mean) * rstd * g0.w + be0.w;
                o1.x = (v[4] - mean) * rstd * g1.x + be1.x;
                o1.y = (v[5] - mean) * rstd * g1.y + be1.y;
                o1.z = (v[6] - mean) * rstd * g1.z + be1.z;
                o1.w = (v[7] - mean) * rstd * g1.w + be1.w;
                *(float4*)&C[(size_t)row * 256 + tx * 4]       = o0;
                *(float4*)&C[(size_t)row * 256 + 128 + tx * 4] = o1;
            }
        }
    } else {
        #pragma unroll
        for (int j = 0; j < 8; j++) {
            int row = m0 + ty * 8 + j;
            if (row < M) {
                float4 o0 = make_float4(acc[j][0], acc[j][1], acc[j][2], acc[j][3]);
                float4 o1 = make_float4(acc[j][4], acc[j][5], acc[j][6], acc[j][7]);
                *(float4*)&C[(size_t)row * 256 + tx * 4]       = o0;
                *(float4*)&C[(size_t)row * 256 + 128 + tx * 4] = o1;
            }
        }
    }
}

// ---------------- K3: scores[b,v] = sum_h W2[h]*tanh(pht[h][b] + ah[v][h]) + b2 ----------------
// grid = V/16 blocks, 256 threads. Half-warp lanes = 16 batches; 2 vocab rows per warp.
__global__ __launch_bounds__(256)
void k_score(const float* __restrict__ W2, const float* __restrict__ b2)
{
    __shared__ float s_pht[H_ * B_];   // 16 KB
    __shared__ float s_ah[16][H_];     // 16 KB
    __shared__ float s_w2[H_];

    int t = threadIdx.x;
    int v0 = blockIdx.x * 16;

    #pragma unroll
    for (int i = t; i < H_ * B_; i += 256) s_pht[i] = g_pht[i];
    s_w2[t & 255] = W2[t & 255];
    // 16 rows x 64 float4 of ah
    for (int i = t; i < 16 * 64; i += 256) {
        int r = i >> 6, c4 = i & 63;
        ((float4*)&s_ah[r][0])[c4] = *(const float4*)&g_ah[(size_t)(v0 + r) * H_ + c4 * 4];
    }
    __syncthreads();

    int w    = t >> 5;
    int lane = t & 31;
    int b    = lane & 15;
    int vsel = lane >> 4;
    int vloc = w * 2 + vsel;

    float acc = b2[0];
    const float4* arow = (const float4*)&s_ah[vloc][0];
    #pragma unroll 4
    for (int h4 = 0; h4 < 64; h4++) {
        float4 av = arow[h4];
        int h = h4 * 4;
        float xs[4] = {av.x, av.y, av.z, av.w};
        #pragma unroll
        for (int i = 0; i < 4; i++) {
            float x = xs[i] + s_pht[(h + i) * B_ + b];
            // tanh(x) = 1 - 2/(exp(2x)+1), via ex2/rcp approx (~1e-6 rel err)
            float e;
            asm("ex2.approx.f32 %0, %1;" : "=f"(e) : "f"(x * 2.8853900817779268f));
            float r;
            asm("rcp.approx.f32 %0, %1;" : "=f"(r) : "f"(e + 1.0f));
            float th = fmaf(-2.0f, r, 1.0f);
            acc = fmaf(s_w2[h + i], th, acc);
        }
    }
    g_scores[(size_t)b * V_ + v0 + vloc] = acc;
}

// ---------------- K4: per-b mean/rstd over V ----------------
__global__ void k_reduce()
{
    int b = blockIdx.x;
    int t = threadIdx.x;
    float s1 = 0.f, s2 = 0.f;
    for (int v = t; v < V_; v += 256) {
        float x = g_scores[(size_t)b * V_ + v];
        s1 += x;
        s2 = fmaf(x, x, s2);
    }
    #pragma unroll
    for (int o = 16; o; o >>= 1) {
        s1 += __shfl_xor_sync(0xffffffffu, s1, o);
        s2 += __shfl_xor_sync(0xffffffffu, s2, o);
    }
    __shared__ float r1[8], r2[8];
    int w = t >> 5, l = t & 31;
    if (l == 0) { r1[w] = s1; r2[w] = s2; }
    __syncthreads();
    if (t == 0) {
        float t1 = 0.f, t2 = 0.f;
        #pragma unroll
        for (int i = 0; i < 8; i++) { t1 += r1[i]; t2 += r2[i]; }
        float mean = t1 * (1.0f / V_);
        float var  = t2 * (1.0f / V_) - mean * mean;
        g_stats[2 * b]     = mean;
        g_stats[2 * b + 1] = rsqrtf(var + EPS_);
    }
}

// ---------------- K5: out = (scores - mean)*rstd*g_pred[v] + b_pred[v] ----------------
__global__ void k_norm(const float* __restrict__ g_pred,
                       const float* __restrict__ b_pred,
                       float* __restrict__ out)
{
    int i = blockIdx.x * 256 + threadIdx.x;
    if (i >= B_ * V_) return;
    int b = i / V_;
    int v = i - b * V_;
    out[i] = (g_scores[i] - g_stats[2 * b]) * g_stats[2 * b + 1] * g_pred[v] + b_pred[v];
}

// ---------------- launch ----------------
extern "C" void kernel_launch(void* const* d_in, const int* in_sizes, int n_in,
                              void* d_out, int out_size)
{
    const float* pe     = (const float*)d_in[0];
    const float* atc4   = (const float*)d_in[1];
    const float* Wp     = (const float*)d_in[2];
    const float* bp     = (const float*)d_in[3];
    const float* gp     = (const float*)d_in[4];
    const float* betap  = (const float*)d_in[5];
    const float* Wa     = (const float*)d_in[6];
    const float* ba     = (const float*)d_in[7];
    const float* ga     = (const float*)d_in[8];
    const float* betaa  = (const float*)d_in[9];
    const float* W1     = (const float*)d_in[10];
    const float* b1     = (const float*)d_in[11];
    const float* W2     = (const float*)d_in[12];
    const float* b2     = (const float*)d_in[13];
    const float* gpred  = (const float*)d_in[14];
    const float* bpred  = (const float*)d_in[15];
    float* out = (float*)d_out;

    float* pa  = nullptr;  // g_a / g_ah accessed via symbols inside kernels
    (void)pa; (void)in_sizes; (void)n_in; (void)out_size;

    // device-global raw pointers for the GEMM kernel outputs
    // (resolved at compile time via the __device__ symbols below)
    k_patient_proj<<<B_, D_>>>(pe, Wp, bp, gp, betap);
    k_patient_head<<<B_, H_>>>(W1, b1);

    // GEMM1: g_a = LN(atc4 @ Wa + ba; ga, betaa)
    {
        void* args_dummy = nullptr; (void)args_dummy;
    }
    // Need addresses of g_a / g_ah on host side: use kernels that reference
    // the symbols directly would be cleaner, but the GEMM is generic. Grab
    // symbol addresses once per launch via cudaGetSymbolAddress equivalents:
    // cudaGetSymbolAddress is a pure query (no allocation, capture-safe).
    static float* p_a  = nullptr;
    static float* p_ah = nullptr;
    if (!p_a)  cudaGetSymbolAddress((void**)&p_a,  g_a);
    if (!p_ah) cudaGetSymbolAddress((void**)&p_ah, g_ah);

    int gblocks = (V_ + 63) / 64;   // 313
    k_gemm<true ><<<gblocks, 256>>>(atc4, Wa, ba, ga, betaa, p_a, V_);
    k_gemm<false><<<gblocks, 256>>>(p_a, W1 + (size_t)D_ * H_, nullptr, nullptr, nullptr, p_ah, V_);

    k_score<<<V_ / 16, 256>>>(W2, b2);
    k_reduce<<<B_, 256>>>();
    k_norm<<<(B_ * V_ + 255) / 256, 256>>>(gpred, bpred, out);
}

// round 3
// speedup vs baseline: 2.0370x; 2.0370x over previous
#include <cuda_runtime.h>
#include <cuda_bf16.h>
#include <cstdint>

#define B_   16
#define V_   20000
#define D_   256
#define H_   256
#define EPS_ 1e-5f

// ======================= helpers =======================
__device__ __forceinline__ uint32_t smem_u32(const void* p) {
    uint32_t a;
    asm("{ .reg .u64 t; cvta.to.shared.u64 t, %1; cvt.u32.u64 %0, t; }" : "=r"(a) : "l"(p));
    return a;
}
__device__ __forceinline__ void ldsm4(uint32_t* r, uint32_t addr) {
    asm volatile("ldmatrix.sync.aligned.m8n8.x4.shared.b16 {%0,%1,%2,%3}, [%4];"
        : "=r"(r[0]), "=r"(r[1]), "=r"(r[2]), "=r"(r[3]) : "r"(addr));
}
__device__ __forceinline__ void ldsm2(uint32_t* r, uint32_t addr) {
    asm volatile("ldmatrix.sync.aligned.m8n8.x2.shared.b16 {%0,%1}, [%2];"
        : "=r"(r[0]), "=r"(r[1]) : "r"(addr));
}
__device__ __forceinline__ void mma_bf16(float* c, const uint32_t* a, const uint32_t* b) {
    asm volatile("mma.sync.aligned.m16n8k16.row.col.f32.bf16.bf16.f32 "
        "{%0,%1,%2,%3}, {%4,%5,%6,%7}, {%8,%9}, {%0,%1,%2,%3};"
        : "+f"(c[0]), "+f"(c[1]), "+f"(c[2]), "+f"(c[3])
        : "r"(a[0]), "r"(a[1]), "r"(a[2]), "r"(a[3]), "r"(b[0]), "r"(b[1]));
}
__device__ __forceinline__ uint32_t pack2bf16(float a, float b) {
    unsigned short ua = __bfloat16_as_ushort(__float2bfloat16(a));
    unsigned short ub = __bfloat16_as_ushort(__float2bfloat16(b));
    return ((uint32_t)ub << 16) | ua;
}

// ======================= scratch =======================
__device__ float g_p[B_ * D_];
__device__ float g_pht[H_ * B_];
__device__ float g_ah[V_ * D_];
__device__ float g_scores[B_ * V_];
__device__ float g_stats[2 * B_];
// pre-split transposed weights: [mat(2)][split(2)][n(256)][k(256)] bf16
__device__ __align__(16) __nv_bfloat16 g_Bt[2 * 2 * 256 * 256];

// ---------------- prep: transpose + split weights ----------------
// grid = 2 (mat), block = 256 (n)
__global__ void k_prep_w(const float* __restrict__ Wa, const float* __restrict__ W1)
{
    int mat = blockIdx.x;
    int n   = threadIdx.x;
    const float* W = mat ? (W1 + (size_t)D_ * H_) : Wa;    // [k][n]
    __nv_bfloat16* dh = g_Bt + ((size_t)(mat * 2 + 0) * 256 + n) * 256;
    __nv_bfloat16* dl = g_Bt + ((size_t)(mat * 2 + 1) * 256 + n) * 256;
    #pragma unroll 4
    for (int k = 0; k < 256; k++) {
        float v = W[(size_t)k * 256 + n];
        __nv_bfloat16 h = __float2bfloat16(v);
        dh[k] = h;
        dl[k] = __float2bfloat16(v - __bfloat162float(h));
    }
}

// ---------------- patient path ----------------
__global__ void k_patient_proj(const float* __restrict__ pe,
                               const float* __restrict__ Wp,
                               const float* __restrict__ bp,
                               const float* __restrict__ gp,
                               const float* __restrict__ betap)
{
    int b = blockIdx.x, d = threadIdx.x;
    __shared__ float s_pe[D_];
    s_pe[d] = pe[b * D_ + d];
    __syncthreads();
    float acc = bp[d];
    #pragma unroll 8
    for (int k = 0; k < D_; k++) acc = fmaf(s_pe[k], Wp[k * D_ + d], acc);
    float s1 = acc, s2 = acc * acc;
    #pragma unroll
    for (int o = 16; o; o >>= 1) {
        s1 += __shfl_xor_sync(0xffffffffu, s1, o);
        s2 += __shfl_xor_sync(0xffffffffu, s2, o);
    }
    __shared__ float r1[8], r2[8], bc[2];
    int w = d >> 5, l = d & 31;
    if (l == 0) { r1[w] = s1; r2[w] = s2; }
    __syncthreads();
    if (d == 0) {
        float t1 = 0.f, t2 = 0.f;
        #pragma unroll
        for (int i = 0; i < 8; i++) { t1 += r1[i]; t2 += r2[i]; }
        float mean = t1 * (1.0f / D_);
        float var  = t2 * (1.0f / D_) - mean * mean;
        bc[0] = mean; bc[1] = rsqrtf(var + EPS_);
    }
    __syncthreads();
    g_p[b * D_ + d] = (acc - bc[0]) * bc[1] * gp[d] + betap[d];
}

__global__ void k_patient_head(const float* __restrict__ W1, const float* __restrict__ b1)
{
    int b = blockIdx.x, h = threadIdx.x;
    __shared__ float s_p[D_];
    s_p[h] = g_p[b * D_ + h];
    __syncthreads();
    float acc = b1[h];
    #pragma unroll 8
    for (int k = 0; k < D_; k++) acc = fmaf(s_p[k], W1[k * H_ + h], acc);
    g_pht[h * B_ + b] = acc;
}

// ---------------- fused HMMA kernel ----------------
// 64-row tile per CTA. Phase 0: X = atc4 @ Wa; LN -> a (bf16 split, back into A smem).
// Phase 1: ah = a @ W1[D:].
//
// smem layout (bytes):
//   A_HI 0      .. 33792   (64 rows x 528B; row = 256 bf16 + 16B pad)
//   A_LO 33792  .. 67584
//   B_HI 67584  .. 88064   (256 rows x 80B; row = 32 bf16 + 16B pad)  [also stats overlay]
//   B_LO 88064  .. 108544
//   P_BA 108544, P_GA 109568, P_BE 110592  (256 floats each)
static constexpr uint32_t A_HI = 0;
static constexpr uint32_t A_LO = 33792;
static constexpr uint32_t B_HI = 67584;
static constexpr uint32_t B_LO = 88064;
static constexpr uint32_t P_BA = 108544;
static constexpr uint32_t P_GA = 109568;
static constexpr uint32_t P_BE = 110592;
static constexpr uint32_t SMEM_SZ = 111616;

__global__ __launch_bounds__(256, 2)
void k_fused(const float* __restrict__ atc4,
             const float* __restrict__ ba,
             const float* __restrict__ ga,
             const float* __restrict__ betaa)
{
    extern __shared__ __align__(16) unsigned char smem[];
    uint32_t sb = smem_u32(smem);
    int tid = threadIdx.x;
    int wid = tid >> 5;
    int l   = tid & 31;
    int wm  = wid >> 2;          // 0..1 : rows wm*32..+31
    int wn  = wid & 3;           // 0..3 : cols wn*64..+63
    int quad = l >> 2;
    int tid4 = l & 3;
    int m0 = blockIdx.x * 64;

    // params to smem
    for (int i = tid; i < 256; i += 256) {
        ((float*)(smem + P_BA))[i] = ba[i];
        ((float*)(smem + P_GA))[i] = ga[i];
        ((float*)(smem + P_BE))[i] = betaa[i];
    }

    // ---- convert atc4 tile -> bf16 hi/lo into A smem ----
    #pragma unroll
    for (int it = 0; it < 8; it++) {
        int id = it * 256 + tid;        // 0..2047
        int row = id >> 5, u = id & 31; // u = 16B unit (8 bf16 = 8 k)
        int gr = m0 + row;
        float f[8];
        if (gr < V_) {
            float4 v0 = *(const float4*)&atc4[(size_t)gr * 256 + u * 8];
            float4 v1 = *(const float4*)&atc4[(size_t)gr * 256 + u * 8 + 4];
            f[0]=v0.x; f[1]=v0.y; f[2]=v0.z; f[3]=v0.w;
            f[4]=v1.x; f[5]=v1.y; f[6]=v1.z; f[7]=v1.w;
        } else {
            #pragma unroll
            for (int i = 0; i < 8; i++) f[i] = 0.f;
        }
        uint4 hp, lp;
        float hf[8], lf[8];
        #pragma unroll
        for (int i = 0; i < 8; i++) {
            hf[i] = __bfloat162float(__float2bfloat16(f[i]));
            lf[i] = f[i] - hf[i];
        }
        hp.x = pack2bf16(hf[0], hf[1]); hp.y = pack2bf16(hf[2], hf[3]);
        hp.z = pack2bf16(hf[4], hf[5]); hp.w = pack2bf16(hf[6], hf[7]);
        lp.x = pack2bf16(lf[0], lf[1]); lp.y = pack2bf16(lf[2], lf[3]);
        lp.z = pack2bf16(lf[4], lf[5]); lp.w = pack2bf16(lf[6], lf[7]);
        uint32_t off = (uint32_t)row * 528 + (uint32_t)u * 16;
        *(uint4*)(smem + A_HI + off) = hp;
        *(uint4*)(smem + A_LO + off) = lp;
    }

    // ldmatrix A base addresses per lane (per m-block); add k0*2 bytes per step
    uint32_t aoff[2];
    {
        uint32_t ar = (uint32_t)(wm * 32 + (l & 15));
        uint32_t kc = (uint32_t)(l >> 4) * 16;
        aoff[0] = sb + A_HI + ar * 528 + kc;
        aoff[1] = sb + A_HI + (ar + 16) * 528 + kc;
    }
    // ldmatrix B base address per lane; add nb*640 + s*32 per use (row stride 80)
    uint32_t boff = sb + B_HI + (uint32_t)(l & 7) * 80 + (uint32_t)((l >> 3) & 1) * 16;

    float acc[8][2][4];

    #pragma unroll 1
    for (int phase = 0; phase < 2; phase++) {
        #pragma unroll
        for (int nb = 0; nb < 8; nb++)
            #pragma unroll
            for (int mb = 0; mb < 2; mb++)
                #pragma unroll
                for (int i = 0; i < 4; i++) acc[nb][mb][i] = 0.f;

        const __nv_bfloat16* bsH = g_Bt + (size_t)(phase * 2 + 0) * 65536;
        const __nv_bfloat16* bsL = g_Bt + (size_t)(phase * 2 + 1) * 65536;

        #pragma unroll 1
        for (int c = 0; c < 8; c++) {          // K chunks of 32
            __syncthreads();
            // load B chunk (hi+lo): 256 rows x 64B each
            #pragma unroll
            for (int it = 0; it < 4; it++) {
                int id = it * 256 + tid;       // 0..1023
                int n = id >> 2, u = id & 3;
                uint32_t dst = (uint32_t)n * 80 + (uint32_t)u * 16;
                *(uint4*)(smem + B_HI + dst) = *(const uint4*)(bsH + (size_t)n * 256 + c * 32 + u * 8);
                *(uint4*)(smem + B_LO + dst) = *(const uint4*)(bsL + (size_t)n * 256 + c * 32 + u * 8);
            }
            __syncthreads();

            #pragma unroll
            for (int s = 0; s < 2; s++) {      // k16 steps
                uint32_t kb = (uint32_t)(c * 64 + s * 32);   // byte offset into A row
                uint32_t ah[2][4], al[2][4];
                ldsm4(ah[0], aoff[0] + kb);
                ldsm4(ah[1], aoff[1] + kb);
                ldsm4(al[0], aoff[0] + 33792 + kb);
                ldsm4(al[1], aoff[1] + 33792 + kb);
                uint32_t bo = boff + (uint32_t)(wn * 64 * 80) + (uint32_t)(s * 32);
                #pragma unroll
                for (int nb = 0; nb < 8; nb++) {
                    uint32_t bh[2], bl[2];
                    ldsm2(bh, bo + (uint32_t)(nb * 8 * 80));
                    ldsm2(bl, bo + (uint32_t)(nb * 8 * 80) + (B_LO - B_HI));
                    #pragma unroll
                    for (int mb = 0; mb < 2; mb++) {
                        mma_bf16(acc[nb][mb], ah[mb], bh);
                        mma_bf16(acc[nb][mb], ah[mb], bl);
                        mma_bf16(acc[nb][mb], al[mb], bh);
                    }
                }
            }
        }
        __syncthreads();   // all mma reads of A/B smem done

        if (phase == 0) {
            // ---- row LN over 256 cols ----
            const float* s_ba = (const float*)(smem + P_BA);
            const float* s_ga = (const float*)(smem + P_GA);
            const float* s_be = (const float*)(smem + P_BE);
            float* psum = (float*)(smem + B_HI);           // [64][4]
            float* psq  = psum + 256;                      // [64][4]
            float* mrs  = psq + 256;                       // [64][2]

            #pragma unroll
            for (int mb = 0; mb < 2; mb++) {
                #pragma unroll
                for (int half = 0; half < 2; half++) {
                    float s1 = 0.f, s2 = 0.f;
                    #pragma unroll
                    for (int nb = 0; nb < 8; nb++) {
                        int col = wn * 64 + nb * 8 + tid4 * 2;
                        float x0 = acc[nb][mb][half * 2 + 0] + s_ba[col];
                        float x1 = acc[nb][mb][half * 2 + 1] + s_ba[col + 1];
                        s1 += x0 + x1;
                        s2 = fmaf(x0, x0, fmaf(x1, x1, s2));
                    }
                    s1 += __shfl_xor_sync(0xffffffffu, s1, 1);
                    s2 += __shfl_xor_sync(0xffffffffu, s2, 1);
                    s1 += __shfl_xor_sync(0xffffffffu, s1, 2);
                    s2 += __shfl_xor_sync(0xffffffffu, s2, 2);
                    if (tid4 == 0) {
                        int row = wm * 32 + mb * 16 + quad + half * 8;
                        psum[row * 4 + wn] = s1;
                        psq[row * 4 + wn]  = s2;
                    }
                }
            }
            __syncthreads();
            if (tid < 64) {
                float s1 = psum[tid * 4] + psum[tid * 4 + 1] + psum[tid * 4 + 2] + psum[tid * 4 + 3];
                float s2 = psq[tid * 4] + psq[tid * 4 + 1] + psq[tid * 4 + 2] + psq[tid * 4 + 3];
                float mean = s1 * (1.0f / 256.0f);
                float var  = s2 * (1.0f / 256.0f) - mean * mean;
                mrs[tid * 2]     = mean;
                mrs[tid * 2 + 1] = rsqrtf(var + EPS_);
            }
            __syncthreads();
            // normalize + re-split into A smem
            #pragma unroll
            for (int mb = 0; mb < 2; mb++) {
                #pragma unroll
                for (int half = 0; half < 2; half++) {
                    int row = wm * 32 + mb * 16 + quad + half * 8;
                    float mean = mrs[row * 2], rstd = mrs[row * 2 + 1];
                    #pragma unroll
                    for (int nb = 0; nb < 8; nb++) {
                        int col = wn * 64 + nb * 8 + tid4 * 2;
                        float x0 = acc[nb][mb][half * 2 + 0] + s_ba[col];
                        float x1 = acc[nb][mb][half * 2 + 1] + s_ba[col + 1];
                        float v0 = (x0 - mean) * rstd * s_ga[col] + s_be[col];
                        float v1 = (x1 - mean) * rstd * s_ga[col + 1] + s_be[col + 1];
                        float h0 = __bfloat162float(__float2bfloat16(v0));
                        float h1 = __bfloat162float(__float2bfloat16(v1));
                        uint32_t off = (uint32_t)row * 528 + (uint32_t)col * 2;
                        *(uint32_t*)(smem + A_HI + off) = pack2bf16(h0, h1);
                        *(uint32_t*)(smem + A_LO + off) = pack2bf16(v0 - h0, v1 - h1);
                    }
                }
            }
            __syncthreads();
        } else {
            // ---- write ah ----
            #pragma unroll
            for (int mb = 0; mb < 2; mb++) {
                #pragma unroll
                for (int half = 0; half < 2; half++) {
                    int row = wm * 32 + mb * 16 + quad + half * 8;
                    int grow = m0 + row;
                    if (grow < V_) {
                        #pragma unroll
                        for (int nb = 0; nb < 8; nb++) {
                            int col = wn * 64 + nb * 8 + tid4 * 2;
                            float2 o = make_float2(acc[nb][mb][half * 2], acc[nb][mb][half * 2 + 1]);
                            *(float2*)&g_ah[(size_t)grow * 256 + col] = o;
                        }
                    }
                }
            }
        }
    }
}

// ---------------- score ----------------
__global__ __launch_bounds__(256)
void k_score(const float* __restrict__ W2, const float* __restrict__ b2)
{
    __shared__ float s_pht[H_ * B_];
    __shared__ float s_ah[16][H_];
    __shared__ float s_w2[H_];

    int t = threadIdx.x;
    int v0 = blockIdx.x * 16;

    #pragma unroll
    for (int i = t; i < H_ * B_; i += 256) s_pht[i] = g_pht[i];
    s_w2[t & 255] = W2[t & 255];
    for (int i = t; i < 16 * 64; i += 256) {
        int r = i >> 6, c4 = i & 63;
        ((float4*)&s_ah[r][0])[c4] = *(const float4*)&g_ah[(size_t)(v0 + r) * H_ + c4 * 4];
    }
    __syncthreads();

    int w = t >> 5, lane = t & 31;
    int b = lane & 15;
    int vloc = w * 2 + (lane >> 4);

    float acc = b2[0];
    const float4* arow = (const float4*)&s_ah[vloc][0];
    #pragma unroll 4
    for (int h4 = 0; h4 < 64; h4++) {
        float4 av = arow[h4];
        int h = h4 * 4;
        float xs[4] = {av.x, av.y, av.z, av.w};
        #pragma unroll
        for (int i = 0; i < 4; i++) {
            float x = xs[i] + s_pht[(h + i) * B_ + b];
            float e;
            asm("ex2.approx.f32 %0, %1;" : "=f"(e) : "f"(x * 2.8853900817779268f));
            float rcp;
            asm("rcp.approx.f32 %0, %1;" : "=f"(rcp) : "f"(e + 1.0f));
            acc = fmaf(s_w2[h + i], fmaf(-2.0f, rcp, 1.0f), acc);
        }
    }
    g_scores[(size_t)b * V_ + v0 + vloc] = acc;
}

// ---------------- per-b mean/rstd over V ----------------
__global__ void k_reduce()
{
    int b = blockIdx.x, t = threadIdx.x;
    float s1 = 0.f, s2 = 0.f;
    for (int v = t; v < V_; v += 256) {
        float x = g_scores[(size_t)b * V_ + v];
        s1 += x; s2 = fmaf(x, x, s2);
    }
    #pragma unroll
    for (int o = 16; o; o >>= 1) {
        s1 += __shfl_xor_sync(0xffffffffu, s1, o);
        s2 += __shfl_xor_sync(0xffffffffu, s2, o);
    }
    __shared__ float r1[8], r2[8];
    int w = t >> 5, ll = t & 31;
    if (ll == 0) { r1[w] = s1; r2[w] = s2; }
    __syncthreads();
    if (t == 0) {
        float t1 = 0.f, t2 = 0.f;
        #pragma unroll
        for (int i = 0; i < 8; i++) { t1 += r1[i]; t2 += r2[i]; }
        float mean = t1 * (1.0f / V_);
        float var  = t2 * (1.0f / V_) - mean * mean;
        g_stats[2 * b] = mean;
        g_stats[2 * b + 1] = rsqrtf(var + EPS_);
    }
}

__global__ void k_norm(const float* __restrict__ g_pred,
                       const float* __restrict__ b_pred,
                       float* __restrict__ out)
{
    int i = blockIdx.x * 256 + threadIdx.x;
    if (i >= B_ * V_) return;
    int b = i / V_;
    int v = i - b * V_;
    out[i] = (g_scores[i] - g_stats[2 * b]) * g_stats[2 * b + 1] * g_pred[v] + b_pred[v];
}

// ---------------- launch ----------------
extern "C" void kernel_launch(void* const* d_in, const int* in_sizes, int n_in,
                              void* d_out, int out_size)
{
    const float* pe     = (const float*)d_in[0];
    const float* atc4   = (const float*)d_in[1];
    const float* Wp     = (const float*)d_in[2];
    const float* bp     = (const float*)d_in[3];
    const float* gp     = (const float*)d_in[4];
    const float* betap  = (const float*)d_in[5];
    const float* Wa     = (const float*)d_in[6];
    const float* ba     = (const float*)d_in[7];
    const float* ga     = (const float*)d_in[8];
    const float* betaa  = (const float*)d_in[9];
    const float* W1     = (const float*)d_in[10];
    const float* b1     = (const float*)d_in[11];
    const float* W2     = (const float*)d_in[12];
    const float* b2     = (const float*)d_in[13];
    const float* gpred  = (const float*)d_in[14];
    const float* bpred  = (const float*)d_in[15];
    float* out = (float*)d_out;
    (void)in_sizes; (void)n_in; (void)out_size;

    static bool attr_set = false;
    if (!attr_set) {
        cudaFuncSetAttribute(k_fused, cudaFuncAttributeMaxDynamicSharedMemorySize, SMEM_SZ);
        attr_set = true;
    }

    k_prep_w<<<2, 256>>>(Wa, W1);
    k_patient_proj<<<B_, D_>>>(pe, Wp, bp, gp, betap);
    k_patient_head<<<B_, H_>>>(W1, b1);

    int tiles = (V_ + 63) / 64;   // 313
    k_fused<<<tiles, 256, SMEM_SZ>>>(atc4, ba, ga, betaa);

    k_score<<<V_ / 16, 256>>>(W2, b2);
    k_reduce<<<B_, 256>>>();
    k_norm<<<(B_ * V_ + 255) / 256, 256>>>(gpred, bpred, out);
}

// round 4
// speedup vs baseline: 2.3932x; 1.1749x over previous
#include <cuda_runtime.h>
#include <cuda_bf16.h>
#include <cstdint>

#define B_   16
#define V_   20000
#define D_   256
#define H_   256
#define EPS_ 1e-5f

// ======================= helpers =======================
__device__ __forceinline__ uint32_t smem_u32(const void* p) {
    uint32_t a;
    asm("{ .reg .u64 t; cvta.to.shared.u64 t, %1; cvt.u32.u64 %0, t; }" : "=r"(a) : "l"(p));
    return a;
}
__device__ __forceinline__ void ldsm4(uint32_t* r, uint32_t addr) {
    asm volatile("ldmatrix.sync.aligned.m8n8.x4.shared.b16 {%0,%1,%2,%3}, [%4];"
        : "=r"(r[0]), "=r"(r[1]), "=r"(r[2]), "=r"(r[3]) : "r"(addr));
}
__device__ __forceinline__ void mma_bf16(float* c, const uint32_t* a, const uint32_t* b) {
    asm volatile("mma.sync.aligned.m16n8k16.row.col.f32.bf16.bf16.f32 "
        "{%0,%1,%2,%3}, {%4,%5,%6,%7}, {%8,%9}, {%0,%1,%2,%3};"
        : "+f"(c[0]), "+f"(c[1]), "+f"(c[2]), "+f"(c[3])
        : "r"(a[0]), "r"(a[1]), "r"(a[2]), "r"(a[3]), "r"(b[0]), "r"(b[1]));
}
__device__ __forceinline__ uint32_t pack2bf16(float a, float b) {
    unsigned short ua = __bfloat16_as_ushort(__float2bfloat16(a));
    unsigned short ub = __bfloat16_as_ushort(__float2bfloat16(b));
    return ((uint32_t)ub << 16) | ua;
}
__device__ __forceinline__ void cp16(uint32_t dst, const void* src) {
    asm volatile("cp.async.cg.shared.global [%0], [%1], 16;" :: "r"(dst), "l"(src));
}
#define CP_COMMIT() asm volatile("cp.async.commit_group;" ::: "memory")
#define CP_WAIT(n)  asm volatile("cp.async.wait_group %0;" :: "n"(n) : "memory")

// ======================= scratch =======================
__device__ float g_p[B_ * D_];
__device__ float g_pht[H_ * B_];
__device__ float g_ah[V_ * D_];
__device__ float g_scores[B_ * V_];
__device__ float g_stats[2 * B_];
// pre-split transposed weights: [mat(2)][split(2)][n(256)][k(256)] bf16
__device__ __align__(16) __nv_bfloat16 g_Bt[2 * 2 * 256 * 256];

// ---------------- prep: transpose + split weights ----------------
__global__ void k_prep_w(const float* __restrict__ Wa, const float* __restrict__ W1)
{
    int mat = blockIdx.x;
    int n   = threadIdx.x;
    const float* W = mat ? (W1 + (size_t)D_ * H_) : Wa;    // [k][n]
    __nv_bfloat16* dh = g_Bt + ((size_t)(mat * 2 + 0) * 256 + n) * 256;
    __nv_bfloat16* dl = g_Bt + ((size_t)(mat * 2 + 1) * 256 + n) * 256;
    #pragma unroll 4
    for (int k = 0; k < 256; k++) {
        float v = W[(size_t)k * 256 + n];
        __nv_bfloat16 h = __float2bfloat16(v);
        dh[k] = h;
        dl[k] = __float2bfloat16(v - __bfloat162float(h));
    }
}

// ---------------- patient path ----------------
__global__ void k_patient_proj(const float* __restrict__ pe,
                               const float* __restrict__ Wp,
                               const float* __restrict__ bp,
                               const float* __restrict__ gp,
                               const float* __restrict__ betap)
{
    int b = blockIdx.x, d = threadIdx.x;
    __shared__ float s_pe[D_];
    s_pe[d] = pe[b * D_ + d];
    __syncthreads();
    float acc = bp[d];
    #pragma unroll 8
    for (int k = 0; k < D_; k++) acc = fmaf(s_pe[k], Wp[k * D_ + d], acc);
    float s1 = acc, s2 = acc * acc;
    #pragma unroll
    for (int o = 16; o; o >>= 1) {
        s1 += __shfl_xor_sync(0xffffffffu, s1, o);
        s2 += __shfl_xor_sync(0xffffffffu, s2, o);
    }
    __shared__ float r1[8], r2[8], bc[2];
    int w = d >> 5, l = d & 31;
    if (l == 0) { r1[w] = s1; r2[w] = s2; }
    __syncthreads();
    if (d == 0) {
        float t1 = 0.f, t2 = 0.f;
        #pragma unroll
        for (int i = 0; i < 8; i++) { t1 += r1[i]; t2 += r2[i]; }
        float mean = t1 * (1.0f / D_);
        float var  = t2 * (1.0f / D_) - mean * mean;
        bc[0] = mean; bc[1] = rsqrtf(var + EPS_);
    }
    __syncthreads();
    g_p[b * D_ + d] = (acc - bc[0]) * bc[1] * gp[d] + betap[d];
}

__global__ void k_patient_head(const float* __restrict__ W1, const float* __restrict__ b1)
{
    int b = blockIdx.x, h = threadIdx.x;
    __shared__ float s_p[D_];
    s_p[h] = g_p[b * D_ + h];
    __syncthreads();
    float acc = b1[h];
    #pragma unroll 8
    for (int k = 0; k < D_; k++) acc = fmaf(s_p[k], W1[k * H_ + h], acc);
    g_pht[h * B_ + b] = acc;
}

// ---------------- fused HMMA kernel ----------------
// 64-row tile per CTA. Phase 0: X = atc4 @ Wa; LN -> a (bf16 split, into A smem).
// Phase 1: ah = a @ W1[D:]. B chunks streamed via cp.async, 3-stage pipeline.
//
// smem layout (bytes):
//   A_HI 0       .. 33792   (64 rows x 528B; row = 256 bf16 + 16B pad)
//   A_LO 33792   .. 67584
//   B bufs: 3 x 40960 at 67584 (each: hi 20480 | lo 20480; 256 rows x 80B)
//   params at 190464; stats at 193536
static constexpr uint32_t A_HI  = 0;
static constexpr uint32_t A_LO  = 33792;
static constexpr uint32_t B_B0  = 67584;
static constexpr uint32_t B_STR = 40960;    // per buffer
static constexpr uint32_t B_LOO = 20480;    // lo offset within buffer
static constexpr uint32_t P_BA  = 190464;
static constexpr uint32_t P_GA  = 191488;
static constexpr uint32_t P_BE  = 192512;
static constexpr uint32_t S_SUM = 193536;   // 256 floats
static constexpr uint32_t S_SQ  = 194560;   // 256 floats
static constexpr uint32_t S_MRS = 195584;   // 128 floats
static constexpr uint32_t SMEM_SZ = 196608;

__global__ __launch_bounds__(256)
void k_fused(const float* __restrict__ atc4,
             const float* __restrict__ ba,
             const float* __restrict__ ga,
             const float* __restrict__ betaa)
{
    extern __shared__ __align__(16) unsigned char smem[];
    uint32_t sb = smem_u32(smem);
    int tid = threadIdx.x;
    int wid = tid >> 5;
    int l   = tid & 31;
    int wm  = wid >> 2;          // 0..1 : rows wm*32..+31
    int wn  = wid & 3;           // 0..3 : cols wn*64..+63
    int quad = l >> 2;
    int tid4 = l & 3;
    int m0 = blockIdx.x * 64;

    // B-chunk issue lambda: chunk index t in [0,16)
    auto issue = [&](int t) {
        int phase = t >> 3, c = t & 7;
        uint32_t bb = sb + B_B0 + (uint32_t)(t % 3) * B_STR;
        const __nv_bfloat16* bsH = g_Bt + (size_t)(phase * 2) * 65536 + c * 32;
        const __nv_bfloat16* bsL = bsH + 65536;
        #pragma unroll
        for (int it = 0; it < 4; it++) {
            int id = it * 256 + tid;
            int n = id >> 2, u = id & 3;
            uint32_t dst = (uint32_t)n * 80 + (uint32_t)u * 16;
            cp16(bb + dst,         bsH + (size_t)n * 256 + u * 8);
            cp16(bb + B_LOO + dst, bsL + (size_t)n * 256 + u * 8);
        }
        CP_COMMIT();
    };

    issue(0);
    issue(1);

    // params to smem
    ((float*)(smem + P_BA))[tid] = ba[tid];
    ((float*)(smem + P_GA))[tid] = ga[tid];
    ((float*)(smem + P_BE))[tid] = betaa[tid];

    // ---- convert atc4 tile -> bf16 hi/lo into A smem (overlaps cp.async) ----
    #pragma unroll
    for (int it = 0; it < 8; it++) {
        int id = it * 256 + tid;        // 0..2047
        int row = id >> 5, u = id & 31; // u = 16B unit (8 bf16)
        int gr = m0 + row;
        float f[8];
        if (gr < V_) {
            float4 v0 = *(const float4*)&atc4[(size_t)gr * 256 + u * 8];
            float4 v1 = *(const float4*)&atc4[(size_t)gr * 256 + u * 8 + 4];
            f[0]=v0.x; f[1]=v0.y; f[2]=v0.z; f[3]=v0.w;
            f[4]=v1.x; f[5]=v1.y; f[6]=v1.z; f[7]=v1.w;
        } else {
            #pragma unroll
            for (int i = 0; i < 8; i++) f[i] = 0.f;
        }
        float hf[8], lf[8];
        #pragma unroll
        for (int i = 0; i < 8; i++) {
            hf[i] = __bfloat162float(__float2bfloat16(f[i]));
            lf[i] = f[i] - hf[i];
        }
        uint4 hp, lp;
        hp.x = pack2bf16(hf[0], hf[1]); hp.y = pack2bf16(hf[2], hf[3]);
        hp.z = pack2bf16(hf[4], hf[5]); hp.w = pack2bf16(hf[6], hf[7]);
        lp.x = pack2bf16(lf[0], lf[1]); lp.y = pack2bf16(lf[2], lf[3]);
        lp.z = pack2bf16(lf[4], lf[5]); lp.w = pack2bf16(lf[6], lf[7]);
        uint32_t off = (uint32_t)row * 528 + (uint32_t)u * 16;
        *(uint4*)(smem + A_HI + off) = hp;
        *(uint4*)(smem + A_LO + off) = lp;
    }

    // ldmatrix A lane addresses (two 16-row m-blocks); +kbyte per step
    uint32_t aoff[2];
    {
        uint32_t ar = (uint32_t)(wm * 32 + (l & 15));
        uint32_t kc = (uint32_t)(l >> 4) * 16;
        aoff[0] = sb + A_HI + ar * 528 + kc;
        aoff[1] = sb + A_HI + (ar + 16) * 528 + kc;
    }
    // ldmatrix B x4 lane address (covers 2 nb blocks x 2 k-halves)
    // lane l: n-row = wn*64 + p*16 + ((l>>4)&1)*8 + (l&7), k-byte = ((l>>3)&1)*16
    uint32_t bbase = (uint32_t)(wn * 64 + ((l >> 4) & 1) * 8 + (l & 7)) * 80
                   + (uint32_t)((l >> 3) & 1) * 16;

    float acc[8][2][4];
    #pragma unroll
    for (int nb = 0; nb < 8; nb++)
        #pragma unroll
        for (int mb = 0; mb < 2; mb++)
            #pragma unroll
            for (int i = 0; i < 4; i++) acc[nb][mb][i] = 0.f;

    #pragma unroll 1
    for (int t = 0; t < 16; t++) {
        int c = t & 7;
        uint32_t bb = sb + B_B0 + (uint32_t)(t % 3) * B_STR;

        if (t == 15) { CP_WAIT(0); } else { CP_WAIT(1); }
        __syncthreads();

        #pragma unroll
        for (int s = 0; s < 2; s++) {
            uint32_t kb = (uint32_t)(c * 64 + s * 32);
            uint32_t ah[2][4], al[2][4];
            ldsm4(ah[0], aoff[0] + kb);
            ldsm4(ah[1], aoff[1] + kb);
            ldsm4(al[0], aoff[0] + (A_LO - A_HI) + kb);
            ldsm4(al[1], aoff[1] + (A_LO - A_HI) + kb);
            uint32_t bo = bb + bbase + (uint32_t)(s * 32);
            #pragma unroll
            for (int p = 0; p < 4; p++) {
                uint32_t rh[4], rl[4];
                ldsm4(rh, bo + (uint32_t)(p * 16 * 80));
                ldsm4(rl, bo + (uint32_t)(p * 16 * 80) + B_LOO);
                #pragma unroll
                for (int q = 0; q < 2; q++) {
                    int nb = p * 2 + q;
                    #pragma unroll
                    for (int mb = 0; mb < 2; mb++) {
                        mma_bf16(acc[nb][mb], ah[mb], &rh[q * 2]);
                        mma_bf16(acc[nb][mb], ah[mb], &rl[q * 2]);
                        mma_bf16(acc[nb][mb], al[mb], &rh[q * 2]);
                    }
                }
            }
        }

        if (t < 14) issue(t + 2);

        if (t == 7) {
            // ---- row LN over 256 cols; re-split into A smem ----
            const float* s_ba = (const float*)(smem + P_BA);
            const float* s_ga = (const float*)(smem + P_GA);
            const float* s_be = (const float*)(smem + P_BE);
            float* psum = (float*)(smem + S_SUM);
            float* psq  = (float*)(smem + S_SQ);
            float* mrs  = (float*)(smem + S_MRS);

            #pragma unroll
            for (int mb = 0; mb < 2; mb++) {
                #pragma unroll
                for (int half = 0; half < 2; half++) {
                    float s1 = 0.f, s2 = 0.f;
                    #pragma unroll
                    for (int nb = 0; nb < 8; nb++) {
                        int col = wn * 64 + nb * 8 + tid4 * 2;
                        float x0 = acc[nb][mb][half * 2 + 0] + s_ba[col];
                        float x1 = acc[nb][mb][half * 2 + 1] + s_ba[col + 1];
                        s1 += x0 + x1;
                        s2 = fmaf(x0, x0, fmaf(x1, x1, s2));
                    }
                    s1 += __shfl_xor_sync(0xffffffffu, s1, 1);
                    s2 += __shfl_xor_sync(0xffffffffu, s2, 1);
                    s1 += __shfl_xor_sync(0xffffffffu, s1, 2);
                    s2 += __shfl_xor_sync(0xffffffffu, s2, 2);
                    if (tid4 == 0) {
                        int row = wm * 32 + mb * 16 + quad + half * 8;
                        psum[row * 4 + wn] = s1;
                        psq[row * 4 + wn]  = s2;
                    }
                }
            }
            __syncthreads();
            if (tid < 64) {
                float s1 = psum[tid * 4] + psum[tid * 4 + 1] + psum[tid * 4 + 2] + psum[tid * 4 + 3];
                float s2 = psq[tid * 4] + psq[tid * 4 + 1] + psq[tid * 4 + 2] + psq[tid * 4 + 3];
                float mean = s1 * (1.0f / 256.0f);
                float var  = s2 * (1.0f / 256.0f) - mean * mean;
                mrs[tid * 2]     = mean;
                mrs[tid * 2 + 1] = rsqrtf(var + EPS_);
            }
            __syncthreads();
            #pragma unroll
            for (int mb = 0; mb < 2; mb++) {
                #pragma unroll
                for (int half = 0; half < 2; half++) {
                    int row = wm * 32 + mb * 16 + quad + half * 8;
                    float mean = mrs[row * 2], rstd = mrs[row * 2 + 1];
                    #pragma unroll
                    for (int nb = 0; nb < 8; nb++) {
                        int col = wn * 64 + nb * 8 + tid4 * 2;
                        float x0 = acc[nb][mb][half * 2 + 0] + s_ba[col];
                        float x1 = acc[nb][mb][half * 2 + 1] + s_ba[col + 1];
                        float v0 = (x0 - mean) * rstd * s_ga[col] + s_be[col];
                        float v1 = (x1 - mean) * rstd * s_ga[col + 1] + s_be[col + 1];
                        float h0 = __bfloat162float(__float2bfloat16(v0));
                        float h1 = __bfloat162float(__float2bfloat16(v1));
                        uint32_t off = (uint32_t)row * 528 + (uint32_t)col * 2;
                        *(uint32_t*)(smem + A_HI + off) = pack2bf16(h0, h1);
                        *(uint32_t*)(smem + A_LO + off) = pack2bf16(v0 - h0, v1 - h1);
                    }
                }
            }
            // reset accumulators for phase 1
            #pragma unroll
            for (int nb = 0; nb < 8; nb++)
                #pragma unroll
                for (int mb = 0; mb < 2; mb++)
                    #pragma unroll
                    for (int i = 0; i < 4; i++) acc[nb][mb][i] = 0.f;
            // A-smem writes ordered before next chunk's mma by the t=8 __syncthreads
        }

        if (t == 15) {
            #pragma unroll
            for (int mb = 0; mb < 2; mb++) {
                #pragma unroll
                for (int half = 0; half < 2; half++) {
                    int row = wm * 32 + mb * 16 + quad + half * 8;
                    int grow = m0 + row;
                    if (grow < V_) {
                        #pragma unroll
                        for (int nb = 0; nb < 8; nb++) {
                            int col = wn * 64 + nb * 8 + tid4 * 2;
                            float2 o = make_float2(acc[nb][mb][half * 2], acc[nb][mb][half * 2 + 1]);
                            *(float2*)&g_ah[(size_t)grow * 256 + col] = o;
                        }
                    }
                }
            }
        }
    }
}

// ---------------- score ----------------
__global__ __launch_bounds__(256)
void k_score(const float* __restrict__ W2, const float* __restrict__ b2)
{
    __shared__ float s_pht[H_ * B_];
    __shared__ float s_ah[16][H_];
    __shared__ float s_w2[H_];

    int t = threadIdx.x;
    int v0 = blockIdx.x * 16;

    #pragma unroll
    for (int i = t; i < H_ * B_; i += 256) s_pht[i] = g_pht[i];
    s_w2[t & 255] = W2[t & 255];
    for (int i = t; i < 16 * 64; i += 256) {
        int r = i >> 6, c4 = i & 63;
        ((float4*)&s_ah[r][0])[c4] = *(const float4*)&g_ah[(size_t)(v0 + r) * H_ + c4 * 4];
    }
    __syncthreads();

    int w = t >> 5, lane = t & 31;
    int b = lane & 15;
    int vloc = w * 2 + (lane >> 4);

    float acc = b2[0];
    const float4* arow = (const float4*)&s_ah[vloc][0];
    #pragma unroll 4
    for (int h4 = 0; h4 < 64; h4++) {
        float4 av = arow[h4];
        int h = h4 * 4;
        float xs[4] = {av.x, av.y, av.z, av.w};
        #pragma unroll
        for (int i = 0; i < 4; i++) {
            float x = xs[i] + s_pht[(h + i) * B_ + b];
            float th;
            asm("tanh.approx.f32 %0, %1;" : "=f"(th) : "f"(x));
            acc = fmaf(s_w2[h + i], th, acc);
        }
    }
    g_scores[(size_t)b * V_ + v0 + vloc] = acc;
}

// ---------------- per-b mean/rstd over V ----------------
__global__ void k_reduce()
{
    int b = blockIdx.x, t = threadIdx.x;
    float s1 = 0.f, s2 = 0.f;
    for (int v = t; v < V_; v += 256) {
        float x = g_scores[(size_t)b * V_ + v];
        s1 += x; s2 = fmaf(x, x, s2);
    }
    #pragma unroll
    for (int o = 16; o; o >>= 1) {
        s1 += __shfl_xor_sync(0xffffffffu, s1, o);
        s2 += __shfl_xor_sync(0xffffffffu, s2, o);
    }
    __shared__ float r1[8], r2[8];
    int w = t >> 5, ll = t & 31;
    if (ll == 0) { r1[w] = s1; r2[w] = s2; }
    __syncthreads();
    if (t == 0) {
        float t1 = 0.f, t2 = 0.f;
        #pragma unroll
        for (int i = 0; i < 8; i++) { t1 += r1[i]; t2 += r2[i]; }
        float mean = t1 * (1.0f / V_);
        float var  = t2 * (1.0f / V_) - mean * mean;
        g_stats[2 * b] = mean;
        g_stats[2 * b + 1] = rsqrtf(var + EPS_);
    }
}

__global__ void k_norm(const float* __restrict__ g_pred,
                       const float* __restrict__ b_pred,
                       float* __restrict__ out)
{
    int i = blockIdx.x * 256 + threadIdx.x;
    if (i >= B_ * V_) return;
    int b = i / V_;
    int v = i - b * V_;
    out[i] = (g_scores[i] - g_stats[2 * b]) * g_stats[2 * b + 1] * g_pred[v] + b_pred[v];
}

// ---------------- launch ----------------
extern "C" void kernel_launch(void* const* d_in, const int* in_sizes, int n_in,
                              void* d_out, int out_size)
{
    const float* pe     = (const float*)d_in[0];
    const float* atc4   = (const float*)d_in[1];
    const float* Wp     = (const float*)d_in[2];
    const float* bp     = (const float*)d_in[3];
    const float* gp     = (const float*)d_in[4];
    const float* betap  = (const float*)d_in[5];
    const float* Wa     = (const float*)d_in[6];
    const float* ba     = (const float*)d_in[7];
    const float* ga     = (const float*)d_in[8];
    const float* betaa  = (const float*)d_in[9];
    const float* W1     = (const float*)d_in[10];
    const float* b1     = (const float*)d_in[11];
    const float* W2     = (const float*)d_in[12];
    const float* b2     = (const float*)d_in[13];
    const float* gpred  = (const float*)d_in[14];
    const float* bpred  = (const float*)d_in[15];
    float* out = (float*)d_out;
    (void)in_sizes; (void)n_in; (void)out_size;

    cudaFuncSetAttribute(k_fused, cudaFuncAttributeMaxDynamicSharedMemorySize, SMEM_SZ);

    k_prep_w<<<2, 256>>>(Wa, W1);
    k_patient_proj<<<B_, D_>>>(pe, Wp, bp, gp, betap);
    k_patient_head<<<B_, H_>>>(W1, b1);

    int tiles = (V_ + 63) / 64;   // 313
    k_fused<<<tiles, 256, SMEM_SZ>>>(atc4, ba, ga, betaa);

    k_score<<<V_ / 16, 256>>>(W2, b2);
    k_reduce<<<B_, 256>>>();
    k_norm<<<(B_ * V_ + 255) / 256, 256>>>(gpred, bpred, out);
}

// round 5
// speedup vs baseline: 2.9526x; 1.2337x over previous
#include <cuda_runtime.h>
#include <cuda_bf16.h>
#include <cstdint>

#define B_   16
#define V_   20000
#define D_   256
#define H_   256
#define EPS_ 1e-5f

// ======================= helpers =======================
__device__ __forceinline__ uint32_t smem_u32(const void* p) {
    uint32_t a;
    asm("{ .reg .u64 t; cvta.to.shared.u64 t, %1; cvt.u32.u64 %0, t; }" : "=r"(a) : "l"(p));
    return a;
}
__device__ __forceinline__ void ldsm4(uint32_t* r, uint32_t addr) {
    asm volatile("ldmatrix.sync.aligned.m8n8.x4.shared.b16 {%0,%1,%2,%3}, [%4];"
        : "=r"(r[0]), "=r"(r[1]), "=r"(r[2]), "=r"(r[3]) : "r"(addr));
}
__device__ __forceinline__ void ldsm4t(uint32_t* r, uint32_t addr) {
    asm volatile("ldmatrix.sync.aligned.m8n8.x4.trans.shared.b16 {%0,%1,%2,%3}, [%4];"
        : "=r"(r[0]), "=r"(r[1]), "=r"(r[2]), "=r"(r[3]) : "r"(addr));
}
__device__ __forceinline__ void mma_bf16(float* c, const uint32_t* a, const uint32_t* b) {
    asm volatile("mma.sync.aligned.m16n8k16.row.col.f32.bf16.bf16.f32 "
        "{%0,%1,%2,%3}, {%4,%5,%6,%7}, {%8,%9}, {%0,%1,%2,%3};"
        : "+f"(c[0]), "+f"(c[1]), "+f"(c[2]), "+f"(c[3])
        : "r"(a[0]), "r"(a[1]), "r"(a[2]), "r"(a[3]), "r"(b[0]), "r"(b[1]));
}
__device__ __forceinline__ uint32_t pack2bf16(float a, float b) {
    unsigned short ua = __bfloat16_as_ushort(__float2bfloat16(a));
    unsigned short ub = __bfloat16_as_ushort(__float2bfloat16(b));
    return ((uint32_t)ub << 16) | ua;
}
__device__ __forceinline__ void cp16(uint32_t dst, const void* src) {
    asm volatile("cp.async.cg.shared.global [%0], [%1], 16;" :: "r"(dst), "l"(src));
}
#define CP_COMMIT() asm volatile("cp.async.commit_group;" ::: "memory")
#define CP_WAIT(n)  asm volatile("cp.async.wait_group %0;" :: "n"(n) : "memory")

// ======================= scratch =======================
__device__ float g_pht[H_ * B_];
__device__ float g_ah[V_ * D_];
__device__ float g_scores[B_ * V_];
__device__ float g_stats[2 * B_];
// split weights, NO transpose: [mat(2)][split(2)][k(256)][n(256)] bf16
__device__ __align__(16) __nv_bfloat16 g_Bs[2 * 2 * 256 * 256];

// ---------------- prep: split weights hi/lo (coalesced both ways) ----------------
// grid = 32 (mat*16 + kg), block = 256 (n)
__global__ void k_prep_w(const float* __restrict__ Wa, const float* __restrict__ W1)
{
    int mat = blockIdx.x >> 4;
    int kg  = blockIdx.x & 15;
    int n   = threadIdx.x;
    const float* W = mat ? (W1 + (size_t)D_ * H_) : Wa;   // [k][n]
    __nv_bfloat16* dh = g_Bs + (size_t)(mat * 2 + 0) * 65536;
    __nv_bfloat16* dl = g_Bs + (size_t)(mat * 2 + 1) * 65536;
    #pragma unroll 4
    for (int kp = 0; kp < 16; kp++) {
        int k = kg * 16 + kp;
        float v = W[(size_t)k * 256 + n];
        __nv_bfloat16 h = __float2bfloat16(v);
        dh[(size_t)k * 256 + n] = h;
        dl[(size_t)k * 256 + n] = __float2bfloat16(v - __bfloat162float(h));
    }
}

// ---------------- patient path: proj + LN + head in one kernel ----------------
__global__ void k_patient(const float* __restrict__ pe,
                          const float* __restrict__ Wp,
                          const float* __restrict__ bp,
                          const float* __restrict__ gp,
                          const float* __restrict__ betap,
                          const float* __restrict__ W1,
                          const float* __restrict__ b1)
{
    int b = blockIdx.x, d = threadIdx.x;
    __shared__ float s_pe[D_], s_p[D_];
    s_pe[d] = pe[b * D_ + d];
    __syncthreads();
    float acc = bp[d];
    #pragma unroll 8
    for (int k = 0; k < D_; k++) acc = fmaf(s_pe[k], Wp[k * D_ + d], acc);
    float s1 = acc, s2 = acc * acc;
    #pragma unroll
    for (int o = 16; o; o >>= 1) {
        s1 += __shfl_xor_sync(0xffffffffu, s1, o);
        s2 += __shfl_xor_sync(0xffffffffu, s2, o);
    }
    __shared__ float r1[8], r2[8], bc[2];
    int w = d >> 5, l = d & 31;
    if (l == 0) { r1[w] = s1; r2[w] = s2; }
    __syncthreads();
    if (d == 0) {
        float t1 = 0.f, t2 = 0.f;
        #pragma unroll
        for (int i = 0; i < 8; i++) { t1 += r1[i]; t2 += r2[i]; }
        float mean = t1 * (1.0f / D_);
        float var  = t2 * (1.0f / D_) - mean * mean;
        bc[0] = mean; bc[1] = rsqrtf(var + EPS_);
    }
    __syncthreads();
    s_p[d] = (acc - bc[0]) * bc[1] * gp[d] + betap[d];
    __syncthreads();
    float acc2 = b1[d];
    #pragma unroll 8
    for (int k = 0; k < D_; k++) acc2 = fmaf(s_p[k], W1[k * H_ + d], acc2);
    g_pht[d * B_ + b] = acc2;
}

// ---------------- fused HMMA kernel ----------------
// 64-row tile, 256 threads, 2 CTAs/SM. K16 chunks, 2-stage cp.async.
// A: swizzled 512B rows (64 rows x 256 bf16), hi at A_HI, lo at A_LO.
// B: [k][n] chunks via ldmatrix.trans; 16 k-rows x 528B per split.
static constexpr uint32_t A_HI  = 0;        // 32768
static constexpr uint32_t A_LO  = 32768;    // 32768
static constexpr uint32_t B_B0  = 65536;
static constexpr uint32_t B_STR = 16896;    // per stage (hi 8448 + lo 8448)
static constexpr uint32_t B_LOO = 8448;
static constexpr uint32_t P_BA  = 99328;
static constexpr uint32_t P_GA  = 100352;
static constexpr uint32_t P_BE  = 101376;
static constexpr uint32_t S_SUM = 102400;   // 64*4 floats
static constexpr uint32_t S_SQ  = 103424;
static constexpr uint32_t S_MRS = 104448;   // 64*2 floats
static constexpr uint32_t SMEM_SZ = 104960;

__global__ __launch_bounds__(256, 2)
void k_fused(const float* __restrict__ atc4,
             const float* __restrict__ ba,
             const float* __restrict__ ga,
             const float* __restrict__ betaa)
{
    extern __shared__ __align__(16) unsigned char smem[];
    uint32_t sb = smem_u32(smem);
    int tid = threadIdx.x;
    int wid = tid >> 5;
    int l   = tid & 31;
    int wm  = wid >> 2;          // 0..1 : rows wm*32..+31
    int wn  = wid & 3;           // 0..3 : cols wn*64..+63
    int quad = l >> 2;
    int tid4 = l & 3;
    int m0 = blockIdx.x * 64;

    // B-chunk issue: t in [0,32)
    auto issue = [&](int t) {
        int phase = t >> 4, c = t & 15;
        uint32_t bb = sb + B_B0 + (uint32_t)(t & 1) * B_STR;
        const __nv_bfloat16* bh = g_Bs + (size_t)(phase * 2) * 65536 + (size_t)c * 16 * 256;
        const __nv_bfloat16* bl = bh + 65536;
        #pragma unroll
        for (int it = 0; it < 2; it++) {
            int id = it * 256 + tid;       // 0..511
            int k = id >> 5, u = id & 31;
            uint32_t dst = (uint32_t)k * 528 + (uint32_t)u * 16;
            cp16(bb + dst,         bh + (size_t)k * 256 + u * 8);
            cp16(bb + B_LOO + dst, bl + (size_t)k * 256 + u * 8);
        }
        CP_COMMIT();
    };

    issue(0);
    issue(1);

    // params to smem
    ((float*)(smem + P_BA))[tid] = ba[tid];
    ((float*)(smem + P_GA))[tid] = ga[tid];
    ((float*)(smem + P_BE))[tid] = betaa[tid];

    // ---- convert atc4 tile -> bf16 hi/lo into swizzled A smem ----
    #pragma unroll
    for (int it = 0; it < 8; it++) {
        int id = it * 256 + tid;        // 0..2047
        int row = id >> 5, u = id & 31;
        int gr = m0 + row;
        float f[8];
        if (gr < V_) {
            float4 v0 = *(const float4*)&atc4[(size_t)gr * 256 + u * 8];
            float4 v1 = *(const float4*)&atc4[(size_t)gr * 256 + u * 8 + 4];
            f[0]=v0.x; f[1]=v0.y; f[2]=v0.z; f[3]=v0.w;
            f[4]=v1.x; f[5]=v1.y; f[6]=v1.z; f[7]=v1.w;
        } else {
            #pragma unroll
            for (int i = 0; i < 8; i++) f[i] = 0.f;
        }
        float hf[8], lf[8];
        #pragma unroll
        for (int i = 0; i < 8; i++) {
            hf[i] = __bfloat162float(__float2bfloat16(f[i]));
            lf[i] = f[i] - hf[i];
        }
        uint4 hp, lp;
        hp.x = pack2bf16(hf[0], hf[1]); hp.y = pack2bf16(hf[2], hf[3]);
        hp.z = pack2bf16(hf[4], hf[5]); hp.w = pack2bf16(hf[6], hf[7]);
        lp.x = pack2bf16(lf[0], lf[1]); lp.y = pack2bf16(lf[2], lf[3]);
        lp.z = pack2bf16(lf[4], lf[5]); lp.w = pack2bf16(lf[6], lf[7]);
        uint32_t off = (uint32_t)row * 512 + (((uint32_t)u ^ ((uint32_t)row & 7)) << 4);
        *(uint4*)(smem + A_HI + off) = hp;
        *(uint4*)(smem + A_LO + off) = lp;
    }

    // A ldmatrix lane addressing (swizzled)
    int ar = wm * 32 + (l & 15);
    uint32_t arx = (uint32_t)(ar & 7);
    uint32_t a_base = sb + A_HI + (uint32_t)ar * 512;
    uint32_t kusel = (uint32_t)((l >> 4) & 1);
    // B ldmatrix.trans lane addressing: rows = k (stride 528), cols = n
    uint32_t b_lane = (uint32_t)(l & 15) * 528 + (uint32_t)(wn * 64 + ((l >> 4) & 1) * 8) * 2;

    float acc[8][2][4];
    #pragma unroll
    for (int nb = 0; nb < 8; nb++)
        #pragma unroll
        for (int mb = 0; mb < 2; mb++)
            #pragma unroll
            for (int i = 0; i < 4; i++) acc[nb][mb][i] = 0.f;

    #pragma unroll 1
    for (int t = 0; t < 32; t++) {
        int c = t & 15;
        uint32_t bb = sb + B_B0 + (uint32_t)(t & 1) * B_STR;

        if (t == 31) { CP_WAIT(0); } else { CP_WAIT(1); }
        __syncthreads();

        uint32_t ku = (uint32_t)(c * 2) + kusel;
        uint32_t aa = a_base + ((ku ^ arx) << 4);
        uint32_t ah0[4], ah1[4], al0[4], al1[4];
        ldsm4(ah0, aa);
        ldsm4(ah1, aa + 8192);
        ldsm4(al0, aa + 32768);
        ldsm4(al1, aa + 40960);
        #pragma unroll
        for (int p = 0; p < 4; p++) {
            uint32_t bo = bb + b_lane + (uint32_t)(p * 32);
            uint32_t rh[4], rl[4];
            ldsm4t(rh, bo);
            ldsm4t(rl, bo + B_LOO);
            #pragma unroll
            for (int q = 0; q < 2; q++) {
                int nb = p * 2 + q;
                mma_bf16(acc[nb][0], ah0, &rh[q * 2]);
                mma_bf16(acc[nb][0], ah0, &rl[q * 2]);
                mma_bf16(acc[nb][0], al0, &rh[q * 2]);
                mma_bf16(acc[nb][1], ah1, &rh[q * 2]);
                mma_bf16(acc[nb][1], ah1, &rl[q * 2]);
                mma_bf16(acc[nb][1], al1, &rh[q * 2]);
            }
        }

        __syncthreads();               // buffer consumed by all warps
        if (t < 30) issue(t + 2);

        if (t == 15) {
            // ---- row LN; re-split into A smem ----
            const float* s_ba = (const float*)(smem + P_BA);
            const float* s_ga = (const float*)(smem + P_GA);
            const float* s_be = (const float*)(smem + P_BE);
            float* psum = (float*)(smem + S_SUM);
            float* psq  = (float*)(smem + S_SQ);
            float* mrs  = (float*)(smem + S_MRS);

            #pragma unroll
            for (int mb = 0; mb < 2; mb++) {
                #pragma unroll
                for (int half = 0; half < 2; half++) {
                    float s1 = 0.f, s2 = 0.f;
                    #pragma unroll
                    for (int nb = 0; nb < 8; nb++) {
                        int col = wn * 64 + nb * 8 + tid4 * 2;
                        float x0 = acc[nb][mb][half * 2 + 0] + s_ba[col];
                        float x1 = acc[nb][mb][half * 2 + 1] + s_ba[col + 1];
                        s1 += x0 + x1;
                        s2 = fmaf(x0, x0, fmaf(x1, x1, s2));
                    }
                    s1 += __shfl_xor_sync(0xffffffffu, s1, 1);
                    s2 += __shfl_xor_sync(0xffffffffu, s2, 1);
                    s1 += __shfl_xor_sync(0xffffffffu, s1, 2);
                    s2 += __shfl_xor_sync(0xffffffffu, s2, 2);
                    if (tid4 == 0) {
                        int row = wm * 32 + mb * 16 + quad + half * 8;
                        psum[row * 4 + wn] = s1;
                        psq[row * 4 + wn]  = s2;
                    }
                }
            }
            __syncthreads();
            if (tid < 64) {
                float s1 = psum[tid * 4] + psum[tid * 4 + 1] + psum[tid * 4 + 2] + psum[tid * 4 + 3];
                float s2 = psq[tid * 4] + psq[tid * 4 + 1] + psq[tid * 4 + 2] + psq[tid * 4 + 3];
                float mean = s1 * (1.0f / 256.0f);
                float var  = s2 * (1.0f / 256.0f) - mean * mean;
                mrs[tid * 2]     = mean;
                mrs[tid * 2 + 1] = rsqrtf(var + EPS_);
            }
            __syncthreads();
            #pragma unroll
            for (int mb = 0; mb < 2; mb++) {
                #pragma unroll
                for (int half = 0; half < 2; half++) {
                    int row = wm * 32 + mb * 16 + quad + half * 8;
                    float mean = mrs[row * 2], rstd = mrs[row * 2 + 1];
                    #pragma unroll
                    for (int nb = 0; nb < 8; nb++) {
                        int col = wn * 64 + nb * 8 + tid4 * 2;
                        float x0 = acc[nb][mb][half * 2 + 0] + s_ba[col];
                        float x1 = acc[nb][mb][half * 2 + 1] + s_ba[col + 1];
                        float v0 = (x0 - mean) * rstd * s_ga[col] + s_be[col];
                        float v1 = (x1 - mean) * rstd * s_ga[col + 1] + s_be[col + 1];
                        float h0 = __bfloat162float(__float2bfloat16(v0));
                        float h1 = __bfloat162float(__float2bfloat16(v1));
                        uint32_t u = (uint32_t)(col >> 3);
                        uint32_t off = (uint32_t)row * 512 + ((u ^ ((uint32_t)row & 7)) << 4)
                                     + (uint32_t)tid4 * 4;
                        *(uint32_t*)(smem + A_HI + off) = pack2bf16(h0, h1);
                        *(uint32_t*)(smem + A_LO + off) = pack2bf16(v0 - h0, v1 - h1);
                    }
                }
            }
            #pragma unroll
            for (int nb = 0; nb < 8; nb++)
                #pragma unroll
                for (int mb = 0; mb < 2; mb++)
                    #pragma unroll
                    for (int i = 0; i < 4; i++) acc[nb][mb][i] = 0.f;
            __syncthreads();           // A rewrite visible before chunk 16 ldsm
        }

        if (t == 31) {
            #pragma unroll
            for (int mb = 0; mb < 2; mb++) {
                #pragma unroll
                for (int half = 0; half < 2; half++) {
                    int row = wm * 32 + mb * 16 + quad + half * 8;
                    int grow = m0 + row;
                    if (grow < V_) {
                        #pragma unroll
                        for (int nb = 0; nb < 8; nb++) {
                            int col = wn * 64 + nb * 8 + tid4 * 2;
                            float2 o = make_float2(acc[nb][mb][half * 2], acc[nb][mb][half * 2 + 1]);
                            *(float2*)&g_ah[(size_t)grow * 256 + col] = o;
                        }
                    }
                }
            }
        }
    }
}

// ---------------- score: scores[b,v] = sum_h W2[h]*tanh(pht[h][b] + ah[v][h]) + b2 ----------------
__global__ __launch_bounds__(256)
void k_score(const float* __restrict__ W2, const float* __restrict__ b2)
{
    __shared__ float  s_pT[16 * 260];    // [b][h], stride 260 floats (2-way max conflict)
    __shared__ float  s_ah[16][H_];
    __shared__ float4 s_w2[64];

    int t = threadIdx.x;
    int v0 = blockIdx.x * 16;

    for (int i = t; i < H_ * B_; i += 256) {
        int h = i >> 4, b = i & 15;
        s_pT[b * 260 + h] = g_pht[i];
    }
    if (t < 64) s_w2[t] = *(const float4*)&W2[t * 4];
    for (int i = t; i < 16 * 64; i += 256) {
        int r = i >> 6, c4 = i & 63;
        ((float4*)&s_ah[r][0])[c4] = *(const float4*)&g_ah[(size_t)(v0 + r) * H_ + c4 * 4];
    }
    __syncthreads();

    int w = t >> 5, lane = t & 31;
    int b = lane & 15;
    int vloc = w * 2 + (lane >> 4);

    const float4* prow = (const float4*)&s_pT[b * 260];
    const float4* arow = (const float4*)&s_ah[vloc][0];
    float acc = b2[0];
    #pragma unroll 8
    for (int h4 = 0; h4 < 64; h4++) {
        float4 av = arow[h4];
        float4 pv = prow[h4];
        float4 wv = s_w2[h4];
        float th;
        asm("tanh.approx.f32 %0, %1;" : "=f"(th) : "f"(av.x + pv.x)); acc = fmaf(wv.x, th, acc);
        asm("tanh.approx.f32 %0, %1;" : "=f"(th) : "f"(av.y + pv.y)); acc = fmaf(wv.y, th, acc);
        asm("tanh.approx.f32 %0, %1;" : "=f"(th) : "f"(av.z + pv.z)); acc = fmaf(wv.z, th, acc);
        asm("tanh.approx.f32 %0, %1;" : "=f"(th) : "f"(av.w + pv.w)); acc = fmaf(wv.w, th, acc);
    }
    g_scores[(size_t)b * V_ + v0 + vloc] = acc;
}

// ---------------- per-b mean/rstd over V ----------------
__global__ void k_reduce()
{
    int b = blockIdx.x, t = threadIdx.x;
    const float4* row = (const float4*)&g_scores[(size_t)b * V_];
    float s1 = 0.f, s2 = 0.f;
    #pragma unroll 4
    for (int v = t; v < V_ / 4; v += 256) {
        float4 x = row[v];
        s1 += x.x + x.y + x.z + x.w;
        s2 = fmaf(x.x, x.x, fmaf(x.y, x.y, fmaf(x.z, x.z, fmaf(x.w, x.w, s2))));
    }
    #pragma unroll
    for (int o = 16; o; o >>= 1) {
        s1 += __shfl_xor_sync(0xffffffffu, s1, o);
        s2 += __shfl_xor_sync(0xffffffffu, s2, o);
    }
    __shared__ float r1[8], r2[8];
    int w = t >> 5, ll = t & 31;
    if (ll == 0) { r1[w] = s1; r2[w] = s2; }
    __syncthreads();
    if (t == 0) {
        float t1 = 0.f, t2 = 0.f;
        #pragma unroll
        for (int i = 0; i < 8; i++) { t1 += r1[i]; t2 += r2[i]; }
        float mean = t1 * (1.0f / V_);
        float var  = t2 * (1.0f / V_) - mean * mean;
        g_stats[2 * b] = mean;
        g_stats[2 * b + 1] = rsqrtf(var + EPS_);
    }
}

__global__ void k_norm(const float* __restrict__ g_pred,
                       const float* __restrict__ b_pred,
                       float* __restrict__ out)
{
    int i = blockIdx.x * 256 + threadIdx.x;
    if (i >= B_ * V_) return;
    int b = i / V_;
    int v = i - b * V_;
    out[i] = (g_scores[i] - g_stats[2 * b]) * g_stats[2 * b + 1] * g_pred[v] + b_pred[v];
}

// ---------------- launch ----------------
extern "C" void kernel_launch(void* const* d_in, const int* in_sizes, int n_in,
                              void* d_out, int out_size)
{
    const float* pe     = (const float*)d_in[0];
    const float* atc4   = (const float*)d_in[1];
    const float* Wp     = (const float*)d_in[2];
    const float* bp     = (const float*)d_in[3];
    const float* gp     = (const float*)d_in[4];
    const float* betap  = (const float*)d_in[5];
    const float* Wa     = (const float*)d_in[6];
    const float* ba     = (const float*)d_in[7];
    const float* ga     = (const float*)d_in[8];
    const float* betaa  = (const float*)d_in[9];
    const float* W1     = (const float*)d_in[10];
    const float* b1     = (const float*)d_in[11];
    const float* W2     = (const float*)d_in[12];
    const float* b2     = (const float*)d_in[13];
    const float* gpred  = (const float*)d_in[14];
    const float* bpred  = (const float*)d_in[15];
    float* out = (float*)d_out;
    (void)in_sizes; (void)n_in; (void)out_size;

    cudaFuncSetAttribute(k_fused, cudaFuncAttributeMaxDynamicSharedMemorySize, SMEM_SZ);

    k_prep_w<<<32, 256>>>(Wa, W1);
    k_patient<<<B_, 256>>>(pe, Wp, bp, gp, betap, W1, b1);

    int tiles = (V_ + 63) / 64;   // 313
    k_fused<<<tiles, 256, SMEM_SZ>>>(atc4, ba, ga, betaa);

    k_score<<<V_ / 16, 256>>>(W2, b2);
    k_reduce<<<B_, 256>>>();
    k_norm<<<(B_ * V_ + 255) / 256, 256>>>(gpred, bpred, out);
}